// round 5
// baseline (speedup 1.0000x reference)
#include <cuda_runtime.h>
#include <cuda_bf16.h>
#include <cstdint>
#include <math.h>

#define BB   2
#define SS   2048
#define DM   2048
#define HQn  32
#define HKVn 8
#define DHn  64
#define ROWS (BB * SS)          // 4096
#define DKV  (HKVn * DHn)       // 512
#define KDIM 2048

#define SCALE_Q (0.125f * 1.44269504088896340736f)   // 1/sqrt(64) * log2(e)

// ---------------- scratch ----------------
__device__ __nv_bfloat16 g_Whi[DM * DM];               // transposed weight hi [N][K]
__device__ __nv_bfloat16 g_Wlo[DM * DM];               // transposed weight lo [N][K]
__device__ __nv_bfloat16 g_Ah[ROWS * DM];              // split activation hi [M][K]
__device__ __nv_bfloat16 g_Al[ROWS * DM];
__device__ __nv_bfloat16 g_Ch[ROWS * DM];              // split attention ctx
__device__ __nv_bfloat16 g_Cl[ROWS * DM];
__device__ __nv_bfloat16 g_Qh[BB * HQn * SS * DHn];    // [b,hq,s,d]
__device__ __nv_bfloat16 g_Ql[BB * HQn * SS * DHn];
__device__ __nv_bfloat16 g_Kh[BB * HKVn * SS * DHn];   // [b,hk,s,d]
__device__ __nv_bfloat16 g_Kl[BB * HKVn * SS * DHn];
__device__ __nv_bfloat16 g_Vh[BB * HKVn * SS * DHn];
__device__ __nv_bfloat16 g_Vl[BB * HKVn * SS * DHn];

// ---------------- helpers ----------------
__device__ __forceinline__ uint32_t smem_u32(const void* p) {
    uint32_t r;
    asm("{ .reg .u64 t; cvta.to.shared.u64 t, %1; cvt.u32.u64 %0, t; }" : "=r"(r) : "l"(p));
    return r;
}
__device__ __forceinline__ uint32_t packbf(float x0, float x1) {
    uint32_t r;   // mem order: low half = x0
    asm("cvt.rn.bf16x2.f32 %0, %1, %2;" : "=r"(r) : "f"(x1), "f"(x0));
    return r;
}
__device__ __forceinline__ void ldsm4(uint32_t a, uint32_t r[4]) {
    asm volatile("ldmatrix.sync.aligned.m8n8.x4.shared.b16 {%0,%1,%2,%3}, [%4];"
                 : "=r"(r[0]), "=r"(r[1]), "=r"(r[2]), "=r"(r[3]) : "r"(a));
}
__device__ __forceinline__ void ldsm4t(uint32_t a, uint32_t r[4]) {
    asm volatile("ldmatrix.sync.aligned.m8n8.x4.trans.shared.b16 {%0,%1,%2,%3}, [%4];"
                 : "=r"(r[0]), "=r"(r[1]), "=r"(r[2]), "=r"(r[3]) : "r"(a));
}
__device__ __forceinline__ void mma_bf16(float c[4], const uint32_t a[4], const uint32_t b[2]) {
    asm volatile("mma.sync.aligned.m16n8k16.row.col.f32.bf16.bf16.f32 "
                 "{%0,%1,%2,%3},{%4,%5,%6,%7},{%8,%9},{%0,%1,%2,%3};"
                 : "+f"(c[0]), "+f"(c[1]), "+f"(c[2]), "+f"(c[3])
                 : "r"(a[0]), "r"(a[1]), "r"(a[2]), "r"(a[3]), "r"(b[0]), "r"(b[1]));
}
__device__ __forceinline__ void cp16(uint32_t dst, const void* src) {
    asm volatile("cp.async.cg.shared.global [%0], [%1], 16;" :: "r"(dst), "l"(src));
}
#define CP_COMMIT() asm volatile("cp.async.commit_group;" ::: "memory")
template<int N> __device__ __forceinline__ void cp_wait() {
    asm volatile("cp.async.wait_group %0;" :: "n"(N) : "memory");
}
__device__ __forceinline__ void split_store(__nv_bfloat16* Ch, __nv_bfloat16* Cl,
                                            size_t idx, float x0, float x1) {
    float h0 = __bfloat162float(__float2bfloat16(x0));
    float h1 = __bfloat162float(__float2bfloat16(x1));
    *(uint32_t*)(Ch + idx) = packbf(x0, x1);
    *(uint32_t*)(Cl + idx) = packbf(x0 - h0, x1 - h1);
}

// ---------------------------------------------------------------------------
// Activation split: X fp32 [M][K] -> Xh, Xl bf16 (elementwise)
// ---------------------------------------------------------------------------
__global__ __launch_bounds__(256)
void aconv(const float* __restrict__ X, __nv_bfloat16* __restrict__ Xh,
           __nv_bfloat16* __restrict__ Xl)
{
    size_t i = ((size_t)blockIdx.x * 256 + threadIdx.x) * 4;
    float4 v = *(const float4*)(X + i);
    float h0 = __bfloat162float(__float2bfloat16(v.x));
    float h1 = __bfloat162float(__float2bfloat16(v.y));
    float h2 = __bfloat162float(__float2bfloat16(v.z));
    float h3 = __bfloat162float(__float2bfloat16(v.w));
    *(uint2*)(Xh + i) = make_uint2(packbf(v.x, v.y), packbf(v.z, v.w));
    *(uint2*)(Xl + i) = make_uint2(packbf(v.x - h0, v.y - h1), packbf(v.z - h2, v.w - h3));
}

// ---------------------------------------------------------------------------
// Weight transpose + bf16 hi/lo split
// ---------------------------------------------------------------------------
__global__ __launch_bounds__(256)
void wconv(const float* __restrict__ W, __nv_bfloat16* __restrict__ Whi,
           __nv_bfloat16* __restrict__ Wlo, int N)
{
    __shared__ float t[32][33];
    int n0 = blockIdx.x * 32, k0 = blockIdx.y * 32;
    int tx = threadIdx.x, ty = threadIdx.y;   // 32 x 8
#pragma unroll
    for (int i = ty; i < 32; i += 8)
        t[i][tx] = W[(size_t)(k0 + i) * N + n0 + tx];
    __syncthreads();
#pragma unroll
    for (int i = ty; i < 32; i += 8) {
        float x = t[tx][i];
        __nv_bfloat16 h = __float2bfloat16(x);
        float hf = __bfloat162float(h);
        Whi[(size_t)(n0 + i) * KDIM + k0 + tx] = h;
        Wlo[(size_t)(n0 + i) * KDIM + k0 + tx] = __float2bfloat16(x - hf);
    }
}

// ---------------------------------------------------------------------------
// HMMA GEMM, all-bf16 operands, 128x128 tile, BK=32, 4-stage cp.async
// pipeline, 3-term hi/lo split.
// MODE 0: fp32 C row-major.  MODE 1: bf16 hi/lo split out (scaled), head-major
//   [b, head, s, d] with NH heads of 64.
// ---------------------------------------------------------------------------
#define ST_SZ   40960
#define A_OFF   0
#define AL_OFF  10240
#define BH_OFF  20480
#define BL_OFF  30720
#define NSTG    4
#define GEMM_SMEM (NSTG * ST_SZ)   // 163840

template<int MODE, int NH>
__global__ __launch_bounds__(256)
void gemm_hmma(const __nv_bfloat16* __restrict__ Ahi, const __nv_bfloat16* __restrict__ Alo,
               const __nv_bfloat16* __restrict__ Bhi, const __nv_bfloat16* __restrict__ Blo,
               float* __restrict__ C,
               __nv_bfloat16* __restrict__ Ch, __nv_bfloat16* __restrict__ Cl,
               float scale, int N)
{
    extern __shared__ char smem[];
    const uint32_t sb = smem_u32(smem);
    const int tid = threadIdx.x;
    const int wid = tid >> 5, lane = tid & 31;
    const int wm = wid >> 2, wn = wid & 3;
    const int m0 = blockIdx.y * 128, n0 = blockIdx.x * 128;

    const __nv_bfloat16* Ahb = Ahi + (size_t)m0 * KDIM;
    const __nv_bfloat16* Alb = Alo + (size_t)m0 * KDIM;
    const __nv_bfloat16* Bhb = Bhi + (size_t)n0 * KDIM;
    const __nv_bfloat16* Blb = Blo + (size_t)n0 * KDIM;

    const uint32_t aRow = (uint32_t)(wm * 64 + (lane & 15)) * 80 + (lane >> 4) * 16;
    const uint32_t bRow = (uint32_t)(wn * 32 + (lane & 7) + (lane >> 4) * 8) * 80
                        + ((lane >> 3) & 1) * 16;

    float acc[4][4][4];
#pragma unroll
    for (int i = 0; i < 4; i++)
#pragma unroll
        for (int j = 0; j < 4; j++)
#pragma unroll
            for (int r = 0; r < 4; r++) acc[i][j][r] = 0.0f;

    // per-stage loader: 512 16B-chunks per operand array, 2 per thread each
    auto load_stage = [&](int c, uint32_t st) {
        int kc = c * 32;
#pragma unroll
        for (int p = 0; p < 2; p++) {
            int ci = tid + p * 256;            // 0..511
            int r = ci >> 2, ch = ci & 3;
            uint32_t d = st + (uint32_t)r * 80 + ch * 16;
            size_t s = (size_t)r * KDIM + kc + ch * 8;
            cp16(d + A_OFF,  Ahb + s);
            cp16(d + AL_OFF, Alb + s);
            cp16(d + BH_OFF, Bhb + s);
            cp16(d + BL_OFF, Blb + s);
        }
    };

    const int NIT = KDIM / 32;   // 64
    load_stage(0, sb);            CP_COMMIT();
    load_stage(1, sb + ST_SZ);    CP_COMMIT();
    load_stage(2, sb + 2*ST_SZ);  CP_COMMIT();

    for (int c = 0; c < NIT; c++) {
        if (c + 3 < NIT) {
            load_stage(c + 3, sb + (uint32_t)((c + 3) & 3) * ST_SZ);
            CP_COMMIT();
            cp_wait<3>();
        } else if (c + 2 < NIT) cp_wait<2>();
        else if (c + 1 < NIT)   cp_wait<1>();
        else                    cp_wait<0>();
        __syncthreads();

        const uint32_t st = sb + (uint32_t)(c & 3) * ST_SZ;
#pragma unroll
        for (int ks = 0; ks < 2; ks++) {
            const uint32_t ko = ks * 32;
            uint32_t ah[4][4], bh[4][2], tmpv[4];
#pragma unroll
            for (int mi = 0; mi < 4; mi++)
                ldsm4(st + A_OFF + aRow + mi * 1280 + ko, ah[mi]);
#pragma unroll
            for (int j = 0; j < 2; j++) {
                ldsm4(st + BH_OFF + bRow + j * 1280 + ko, tmpv);
                bh[2*j][0] = tmpv[0]; bh[2*j][1] = tmpv[1];
                bh[2*j+1][0] = tmpv[2]; bh[2*j+1][1] = tmpv[3];
            }
#pragma unroll
            for (int mi = 0; mi < 4; mi++)
#pragma unroll
                for (int nj = 0; nj < 4; nj++)
                    mma_bf16(acc[mi][nj], ah[mi], bh[nj]);

            uint32_t bl[4][2];
#pragma unroll
            for (int j = 0; j < 2; j++) {
                ldsm4(st + BL_OFF + bRow + j * 1280 + ko, tmpv);
                bl[2*j][0] = tmpv[0]; bl[2*j][1] = tmpv[1];
                bl[2*j+1][0] = tmpv[2]; bl[2*j+1][1] = tmpv[3];
            }
#pragma unroll
            for (int mi = 0; mi < 4; mi++)
#pragma unroll
                for (int nj = 0; nj < 4; nj++)
                    mma_bf16(acc[mi][nj], ah[mi], bl[nj]);

            uint32_t al[4][4];
#pragma unroll
            for (int mi = 0; mi < 4; mi++)
                ldsm4(st + AL_OFF + aRow + mi * 1280 + ko, al[mi]);
#pragma unroll
            for (int mi = 0; mi < 4; mi++)
#pragma unroll
                for (int nj = 0; nj < 4; nj++)
                    mma_bf16(acc[mi][nj], al[mi], bh[nj]);
        }
        __syncthreads();
    }

    const int rbase = m0 + wm * 64 + (lane >> 2);
    const int cbase = n0 + wn * 32 + (lane & 3) * 2;
#pragma unroll
    for (int mi = 0; mi < 4; mi++)
#pragma unroll
        for (int nj = 0; nj < 4; nj++) {
            int r0 = rbase + mi * 16;
            int cc = cbase + nj * 8;
            if (MODE == 0) {
                *(float2*)(C + (size_t)r0 * N + cc)       = make_float2(acc[mi][nj][0], acc[mi][nj][1]);
                *(float2*)(C + (size_t)(r0 + 8) * N + cc) = make_float2(acc[mi][nj][2], acc[mi][nj][3]);
            } else {
                int bb0 = r0 >> 11, ss0 = r0 & 2047;
                int hh = cc >> 6, dd = cc & 63;
                size_t i0 = (((size_t)(bb0 * NH + hh)) * SS + ss0) * 64 + dd;
                int r1 = r0 + 8;
                int bb1 = r1 >> 11, ss1 = r1 & 2047;
                size_t i1 = (((size_t)(bb1 * NH + hh)) * SS + ss1) * 64 + dd;
                split_store(Ch, Cl, i0, acc[mi][nj][0] * scale, acc[mi][nj][1] * scale);
                split_store(Ch, Cl, i1, acc[mi][nj][2] * scale, acc[mi][nj][3] * scale);
            }
        }
}

// ---------------------------------------------------------------------------
// HMMA flash attention (R4, epilogue now writes split bf16 ctx)
// ---------------------------------------------------------------------------
#define AT_STRIDE 144
#define AT_KH 0
#define AT_KL 9216
#define AT_VH 18432
#define AT_VL 27648
#define AT_STAGE 36864
#define ATT_SMEM (2 * AT_STAGE)   // 73728

__global__ __launch_bounds__(256, 1)
void attn_mma(const __nv_bfloat16* __restrict__ Qh_, const __nv_bfloat16* __restrict__ Ql_,
              const __nv_bfloat16* __restrict__ Kh_, const __nv_bfloat16* __restrict__ Kl_,
              const __nv_bfloat16* __restrict__ Vh_, const __nv_bfloat16* __restrict__ Vl_,
              __nv_bfloat16* __restrict__ Ch, __nv_bfloat16* __restrict__ Cl)
{
    extern __shared__ char smem[];
    const uint32_t sb = smem_u32(smem);
    const int tid = threadIdx.x, wid = tid >> 5, lane = tid & 31;
    const int bh = blockIdx.y;
    const int b = bh >> 5, hq = bh & 31, hk = hq >> 2;
    const int q0 = blockIdx.x * 128;

    const __nv_bfloat16* Qhb = Qh_ + ((size_t)bh * SS + q0) * 64;
    const __nv_bfloat16* Qlb = Ql_ + ((size_t)bh * SS + q0) * 64;
    const size_t kvoff = (size_t)(b * HKVn + hk) * SS * 64;
    const __nv_bfloat16* Khb = Kh_ + kvoff;
    const __nv_bfloat16* Klb = Kl_ + kvoff;
    const __nv_bfloat16* Vhb = Vh_ + kvoff;
    const __nv_bfloat16* Vlb = Vl_ + kvoff;

    for (int i = tid; i < 1024; i += 256) {
        int r = i >> 3, ch = i & 7;
        *(uint4*)(smem + r * AT_STRIDE + ch * 16)         = *(const uint4*)(Qhb + (size_t)r * 64 + ch * 8);
        *(uint4*)(smem + 18432 + r * AT_STRIDE + ch * 16) = *(const uint4*)(Qlb + (size_t)r * 64 + ch * 8);
    }
    __syncthreads();

    uint32_t qh[4][4], ql[4][4];
    {
        uint32_t aAddr = sb + (uint32_t)(wid * 16 + (lane & 15)) * AT_STRIDE + (lane >> 4) * 16;
#pragma unroll
        for (int kc = 0; kc < 4; kc++) {
            ldsm4(aAddr + kc * 32, qh[kc]);
            ldsm4(aAddr + 18432 + kc * 32, ql[kc]);
        }
    }
    __syncthreads();

    auto load_tile = [&](int kt, uint32_t st) {
        size_t base = (size_t)kt * 64 * 64;
#pragma unroll
        for (int i = tid; i < 512; i += 256) {
            int r = i >> 3, ch = i & 7;
            uint32_t d = st + r * AT_STRIDE + ch * 16;
            size_t s = base + (size_t)r * 64 + ch * 8;
            cp16(d + AT_KH, Khb + s);
            cp16(d + AT_KL, Klb + s);
            cp16(d + AT_VH, Vhb + s);
            cp16(d + AT_VL, Vlb + s);
        }
    };

    float m0 = -1e30f, m1 = -1e30f, l0 = 0.0f, l1 = 0.0f;
    float ctx[8][4];
#pragma unroll
    for (int j = 0; j < 8; j++)
#pragma unroll
        for (int e = 0; e < 4; e++) ctx[j][e] = 0.0f;

    load_tile(0, sb);
    CP_COMMIT();

    const int NKT = SS / 64;
    for (int kt = 0; kt < NKT; kt++) {
        const uint32_t st = sb + (uint32_t)(kt & 1) * AT_STAGE;
        if (kt + 1 < NKT) {
            load_tile(kt + 1, sb + (uint32_t)((kt + 1) & 1) * AT_STAGE);
            CP_COMMIT();
            cp_wait<1>();
        } else {
            cp_wait<0>();
        }
        __syncthreads();

        float sS[8][4];
#pragma unroll
        for (int j = 0; j < 8; j++)
#pragma unroll
            for (int e = 0; e < 4; e++) sS[j][e] = 0.0f;

        const uint32_t kAddr = st + (uint32_t)((lane >> 4) * 8 + (lane & 7)) * AT_STRIDE
                             + ((lane >> 3) & 1) * 16;
#pragma unroll
        for (int kc = 0; kc < 4; kc++) {
            uint32_t bKh[8][2], bKl[8][2], t[4];
#pragma unroll
            for (int np = 0; np < 4; np++) {
                ldsm4(kAddr + AT_KH + np * 2304 + kc * 32, t);
                bKh[2*np][0] = t[0]; bKh[2*np][1] = t[1];
                bKh[2*np+1][0] = t[2]; bKh[2*np+1][1] = t[3];
                ldsm4(kAddr + AT_KL + np * 2304 + kc * 32, t);
                bKl[2*np][0] = t[0]; bKl[2*np][1] = t[1];
                bKl[2*np+1][0] = t[2]; bKl[2*np+1][1] = t[3];
            }
#pragma unroll
            for (int nj = 0; nj < 8; nj++) mma_bf16(sS[nj], qh[kc], bKh[nj]);
#pragma unroll
            for (int nj = 0; nj < 8; nj++) mma_bf16(sS[nj], ql[kc], bKh[nj]);
#pragma unroll
            for (int nj = 0; nj < 8; nj++) mma_bf16(sS[nj], qh[kc], bKl[nj]);
        }

        float mx0 = -1e30f, mx1 = -1e30f;
#pragma unroll
        for (int j = 0; j < 8; j++) {
            mx0 = fmaxf(mx0, fmaxf(sS[j][0], sS[j][1]));
            mx1 = fmaxf(mx1, fmaxf(sS[j][2], sS[j][3]));
        }
        mx0 = fmaxf(mx0, __shfl_xor_sync(0xffffffffu, mx0, 1));
        mx0 = fmaxf(mx0, __shfl_xor_sync(0xffffffffu, mx0, 2));
        mx1 = fmaxf(mx1, __shfl_xor_sync(0xffffffffu, mx1, 1));
        mx1 = fmaxf(mx1, __shfl_xor_sync(0xffffffffu, mx1, 2));

        float mn0 = fmaxf(m0, mx0), mn1 = fmaxf(m1, mx1);
        float al0 = exp2f(m0 - mn0), al1 = exp2f(m1 - mn1);
        m0 = mn0; m1 = mn1;

        float rs0 = 0.0f, rs1 = 0.0f;
#pragma unroll
        for (int j = 0; j < 8; j++) {
            sS[j][0] = exp2f(sS[j][0] - mn0);
            sS[j][1] = exp2f(sS[j][1] - mn0);
            sS[j][2] = exp2f(sS[j][2] - mn1);
            sS[j][3] = exp2f(sS[j][3] - mn1);
            rs0 += sS[j][0] + sS[j][1];
            rs1 += sS[j][2] + sS[j][3];
        }
        rs0 += __shfl_xor_sync(0xffffffffu, rs0, 1);
        rs0 += __shfl_xor_sync(0xffffffffu, rs0, 2);
        rs1 += __shfl_xor_sync(0xffffffffu, rs1, 1);
        rs1 += __shfl_xor_sync(0xffffffffu, rs1, 2);
        l0 = l0 * al0 + rs0;
        l1 = l1 * al1 + rs1;

#pragma unroll
        for (int j = 0; j < 8; j++) {
            ctx[j][0] *= al0; ctx[j][1] *= al0;
            ctx[j][2] *= al1; ctx[j][3] *= al1;
        }

        const uint32_t vAddr = st + AT_VH + (uint32_t)(lane & 15) * AT_STRIDE + (lane >> 4) * 16;
#pragma unroll
        for (int kc = 0; kc < 4; kc++) {
            float x0 = sS[2*kc][0],   x1 = sS[2*kc][1],   x2 = sS[2*kc][2],   x3 = sS[2*kc][3];
            float y0 = sS[2*kc+1][0], y1 = sS[2*kc+1][1], y2 = sS[2*kc+1][2], y3 = sS[2*kc+1][3];
            uint32_t aPh[4], aPl[4];
            aPh[0] = packbf(x0, x1); aPh[1] = packbf(x2, x3);
            aPh[2] = packbf(y0, y1); aPh[3] = packbf(y2, y3);
            float hx0 = __bfloat162float(__float2bfloat16(x0));
            float hx1 = __bfloat162float(__float2bfloat16(x1));
            float hx2 = __bfloat162float(__float2bfloat16(x2));
            float hx3 = __bfloat162float(__float2bfloat16(x3));
            float hy0 = __bfloat162float(__float2bfloat16(y0));
            float hy1 = __bfloat162float(__float2bfloat16(y1));
            float hy2 = __bfloat162float(__float2bfloat16(y2));
            float hy3 = __bfloat162float(__float2bfloat16(y3));
            aPl[0] = packbf(x0 - hx0, x1 - hx1); aPl[1] = packbf(x2 - hx2, x3 - hx3);
            aPl[2] = packbf(y0 - hy0, y1 - hy1); aPl[3] = packbf(y2 - hy2, y3 - hy3);

#pragma unroll
            for (int dp = 0; dp < 4; dp++) {
                uint32_t t[4];
                ldsm4t(vAddr + kc * 2304 + dp * 32, t);
                uint32_t b0[2] = { t[0], t[1] }, b1[2] = { t[2], t[3] };
                mma_bf16(ctx[2*dp],   aPh, b0);
                mma_bf16(ctx[2*dp+1], aPh, b1);
                mma_bf16(ctx[2*dp],   aPl, b0);
                mma_bf16(ctx[2*dp+1], aPl, b1);
                ldsm4t(vAddr + (AT_VL - AT_VH) + kc * 2304 + dp * 32, t);
                uint32_t c0[2] = { t[0], t[1] }, c1[2] = { t[2], t[3] };
                mma_bf16(ctx[2*dp],   aPh, c0);
                mma_bf16(ctx[2*dp+1], aPh, c1);
            }
        }
        __syncthreads();
    }

    // epilogue: normalize, write split bf16 ctx [b, s, hq*64+d]
    float inv0 = 1.0f / l0, inv1 = 1.0f / l1;
    int r0 = q0 + wid * 16 + (lane >> 2);
    size_t obase = (size_t)b * SS * DM + (size_t)hq * 64;
#pragma unroll
    for (int nj = 0; nj < 8; nj++) {
        int cc = nj * 8 + (lane & 3) * 2;
        split_store(Ch, Cl, obase + (size_t)r0 * DM + cc,
                    ctx[nj][0] * inv0, ctx[nj][1] * inv0);
        split_store(Ch, Cl, obase + (size_t)(r0 + 8) * DM + cc,
                    ctx[nj][2] * inv1, ctx[nj][3] * inv1);
    }
}

// ---------------------------------------------------------------------------
extern "C" void kernel_launch(void* const* d_in, const int* in_sizes, int n_in,
                              void* d_out, int out_size)
{
    const float* q  = (const float*)d_in[0];
    const float* k  = (const float*)d_in[1];
    const float* v  = (const float*)d_in[2];
    const float* Wq = (const float*)d_in[3];
    const float* Wk = (const float*)d_in[4];
    const float* Wv = (const float*)d_in[5];
    const float* Wo = (const float*)d_in[6];
    float* out = (float*)d_out;

    __nv_bfloat16 *Whi, *Wlo, *Ah, *Al, *Ch, *Cl, *Qh, *Ql, *Kh, *Kl, *Vh, *Vl;
    cudaGetSymbolAddress((void**)&Whi, g_Whi);
    cudaGetSymbolAddress((void**)&Wlo, g_Wlo);
    cudaGetSymbolAddress((void**)&Ah, g_Ah);
    cudaGetSymbolAddress((void**)&Al, g_Al);
    cudaGetSymbolAddress((void**)&Ch, g_Ch);
    cudaGetSymbolAddress((void**)&Cl, g_Cl);
    cudaGetSymbolAddress((void**)&Qh, g_Qh);
    cudaGetSymbolAddress((void**)&Ql, g_Ql);
    cudaGetSymbolAddress((void**)&Kh, g_Kh);
    cudaGetSymbolAddress((void**)&Kl, g_Kl);
    cudaGetSymbolAddress((void**)&Vh, g_Vh);
    cudaGetSymbolAddress((void**)&Vl, g_Vl);

    cudaFuncSetAttribute((const void*)&gemm_hmma<0,0>,  cudaFuncAttributeMaxDynamicSharedMemorySize, GEMM_SMEM);
    cudaFuncSetAttribute((const void*)&gemm_hmma<1,32>, cudaFuncAttributeMaxDynamicSharedMemorySize, GEMM_SMEM);
    cudaFuncSetAttribute((const void*)&gemm_hmma<1,8>,  cudaFuncAttributeMaxDynamicSharedMemorySize, GEMM_SMEM);
    cudaFuncSetAttribute((const void*)&attn_mma,        cudaFuncAttributeMaxDynamicSharedMemorySize, ATT_SMEM);

    dim3 wblk(32, 8);
    const int ACONV_GRID = (ROWS * DM / 4) / 256;   // 8192

    // Q projection
    aconv<<<ACONV_GRID, 256>>>(q, Ah, Al);
    wconv<<<dim3(DM / 32, KDIM / 32), wblk>>>(Wq, Whi, Wlo, DM);
    gemm_hmma<1,32><<<dim3(DM / 128, ROWS / 128), 256, GEMM_SMEM>>>(
        Ah, Al, Whi, Wlo, nullptr, Qh, Ql, SCALE_Q, DM);

    // K projection
    aconv<<<ACONV_GRID, 256>>>(k, Ah, Al);
    wconv<<<dim3(DKV / 32, KDIM / 32), wblk>>>(Wk, Whi, Wlo, DKV);
    gemm_hmma<1,8><<<dim3(DKV / 128, ROWS / 128), 256, GEMM_SMEM>>>(
        Ah, Al, Whi, Wlo, nullptr, Kh, Kl, 1.0f, DKV);

    // V projection
    aconv<<<ACONV_GRID, 256>>>(v, Ah, Al);
    wconv<<<dim3(DKV / 32, KDIM / 32), wblk>>>(Wv, Whi, Wlo, DKV);
    gemm_hmma<1,8><<<dim3(DKV / 128, ROWS / 128), 256, GEMM_SMEM>>>(
        Ah, Al, Whi, Wlo, nullptr, Vh, Vl, 1.0f, DKV);

    // attention (writes split ctx)
    attn_mma<<<dim3(SS / 128, BB * HQn), 256, ATT_SMEM>>>(Qh, Ql, Kh, Kl, Vh, Vl, Ch, Cl);

    // output projection
    wconv<<<dim3(DM / 32, KDIM / 32), wblk>>>(Wo, Whi, Wlo, DM);
    gemm_hmma<0,0><<<dim3(DM / 128, ROWS / 128), 256, GEMM_SMEM>>>(
        Ch, Cl, Whi, Wlo, out, nullptr, nullptr, 1.0f, DM);
}

// round 6
// speedup vs baseline: 1.5841x; 1.5841x over previous
#include <cuda_runtime.h>
#include <cuda_fp16.h>
#include <cstdint>
#include <math.h>

#define BB   2
#define SS   2048
#define DM   2048
#define HQn  32
#define HKVn 8
#define DHn  64
#define ROWS (BB * SS)          // 4096
#define DKV  (HKVn * DHn)       // 512
#define KDIM 2048

#define SCALE_Q (0.125f * 1.44269504088896340736f)   // 1/sqrt(64) * log2(e)

// ---------------- scratch ----------------
__device__ __half g_Wf[DM * DM];                 // transposed weight fp16 [N][K]
__device__ __half g_Ch[ROWS * DM];               // split attention ctx hi
__device__ __half g_Cl[ROWS * DM];               // split attention ctx lo
__device__ __half g_Qh[BB * HQn * SS * DHn];     // [b,hq,s,d] split
__device__ __half g_Ql[BB * HQn * SS * DHn];
__device__ __half g_Kf[BB * HKVn * SS * DHn];    // [b,hk,s,d] single fp16
__device__ __half g_Vf[BB * HKVn * SS * DHn];

// ---------------- helpers ----------------
__device__ __forceinline__ uint32_t smem_u32(const void* p) {
    uint32_t r;
    asm("{ .reg .u64 t; cvta.to.shared.u64 t, %1; cvt.u32.u64 %0, t; }" : "=r"(r) : "l"(p));
    return r;
}
__device__ __forceinline__ uint32_t packh(float x0, float x1) {
    uint32_t r;   // mem order: low half = x0
    asm("cvt.rn.f16x2.f32 %0, %1, %2;" : "=r"(r) : "f"(x1), "f"(x0));
    return r;
}
__device__ __forceinline__ void sts64(uint32_t a, uint32_t x, uint32_t y) {
    asm volatile("st.shared.v2.b32 [%0], {%1,%2};" :: "r"(a), "r"(x), "r"(y));
}
__device__ __forceinline__ void sts128(uint32_t a, uint4 v) {
    asm volatile("st.shared.v4.b32 [%0], {%1,%2,%3,%4};"
                 :: "r"(a), "r"(v.x), "r"(v.y), "r"(v.z), "r"(v.w));
}
__device__ __forceinline__ void ldsm4(uint32_t a, uint32_t r[4]) {
    asm volatile("ldmatrix.sync.aligned.m8n8.x4.shared.b16 {%0,%1,%2,%3}, [%4];"
                 : "=r"(r[0]), "=r"(r[1]), "=r"(r[2]), "=r"(r[3]) : "r"(a));
}
__device__ __forceinline__ void ldsm4t(uint32_t a, uint32_t r[4]) {
    asm volatile("ldmatrix.sync.aligned.m8n8.x4.trans.shared.b16 {%0,%1,%2,%3}, [%4];"
                 : "=r"(r[0]), "=r"(r[1]), "=r"(r[2]), "=r"(r[3]) : "r"(a));
}
__device__ __forceinline__ void mma_f16(float c[4], const uint32_t a[4], const uint32_t b[2]) {
    asm volatile("mma.sync.aligned.m16n8k16.row.col.f32.f16.f16.f32 "
                 "{%0,%1,%2,%3},{%4,%5,%6,%7},{%8,%9},{%0,%1,%2,%3};"
                 : "+f"(c[0]), "+f"(c[1]), "+f"(c[2]), "+f"(c[3])
                 : "r"(a[0]), "r"(a[1]), "r"(a[2]), "r"(a[3]), "r"(b[0]), "r"(b[1]));
}
__device__ __forceinline__ void cp16(uint32_t dst, const void* src) {
    asm volatile("cp.async.cg.shared.global [%0], [%1], 16;" :: "r"(dst), "l"(src));
}
#define CP_COMMIT() asm volatile("cp.async.commit_group;" ::: "memory")
template<int N> __device__ __forceinline__ void cp_wait() {
    asm volatile("cp.async.wait_group %0;" :: "n"(N) : "memory");
}
__device__ __forceinline__ void split_store_h(__half* Ch, __half* Cl,
                                              size_t idx, float x0, float x1) {
    float h0 = __half2float(__float2half(x0));
    float h1 = __half2float(__float2half(x1));
    *(uint32_t*)(Ch + idx) = packh(x0, x1);
    *(uint32_t*)(Cl + idx) = packh(x0 - h0, x1 - h1);
}

// ---------------------------------------------------------------------------
// Weight transpose + fp16 round:  Wf[n][k] = (half) W[k][n]
// ---------------------------------------------------------------------------
__global__ __launch_bounds__(256)
void wconv(const float* __restrict__ W, __half* __restrict__ Wf, int N)
{
    __shared__ float t[32][33];
    int n0 = blockIdx.x * 32, k0 = blockIdx.y * 32;
    int tx = threadIdx.x, ty = threadIdx.y;   // 32 x 8
#pragma unroll
    for (int i = ty; i < 32; i += 8)
        t[i][tx] = W[(size_t)(k0 + i) * N + n0 + tx];
    __syncthreads();
#pragma unroll
    for (int i = ty; i < 32; i += 8)
        Wf[(size_t)(n0 + i) * KDIM + k0 + tx] = __float2half(t[tx][i]);
}

// ---------------------------------------------------------------------------
// HMMA GEMM, 128x128 tile, BK=32, double-buffered smem, 2-term fp16 split
// (A = Ah + Al exact, B single rounded fp16).
// AIN  0: A fp32, converted inline.  1: A pre-split fp16 pair (Ahg, Alg).
// OUTK 0: fp32 C row-major.
//      1: split fp16 hi/lo, scaled, head-major [b, head, s, d] (NH heads).
//      2: single fp16, head-major.
// ---------------------------------------------------------------------------
#define ST_SZ   30720
#define AH_OFF  0
#define AL_OFF  10240
#define B_OFF   20480
#define GEMM_SMEM (2 * ST_SZ)   // 61440

template<int AIN, int OUTK, int NH>
__global__ __launch_bounds__(256)
void gemm_hmma(const float* __restrict__ Af,
               const __half* __restrict__ Ahg, const __half* __restrict__ Alg,
               const __half* __restrict__ Bf, float* __restrict__ C,
               __half* __restrict__ Ch, __half* __restrict__ Cl,
               float scale, int N)
{
    extern __shared__ char smem[];
    const uint32_t sb = smem_u32(smem);
    const int tid = threadIdx.x;
    const int wid = tid >> 5, lane = tid & 31;
    const int wm = wid >> 2, wn = wid & 3;
    const int m0 = blockIdx.y * 128, n0 = blockIdx.x * 128;

    // global-load mappings
    const int arow = tid >> 3, acol = (tid & 7) * 4;   // fp32 A: 4 rows stride 32
    const int hrow = tid >> 2, hcol = (tid & 3) * 8;   // fp16 rows: 2 rows stride 64

    const float* Afb = Af + (size_t)(m0 + arow) * KDIM + acol;
    const __half* Ahb = Ahg + (size_t)(m0 + hrow) * KDIM + hcol;
    const __half* Alb = Alg + (size_t)(m0 + hrow) * KDIM + hcol;
    const __half* Bfb = Bf + (size_t)(n0 + hrow) * KDIM + hcol;

    const uint32_t aRow = (uint32_t)(wm * 64 + (lane & 15)) * 80 + (lane >> 4) * 16;
    const uint32_t bRow = (uint32_t)(wn * 32 + (lane & 7) + (lane >> 4) * 8) * 80
                        + ((lane >> 3) & 1) * 16;

    float acc[4][4][4];
#pragma unroll
    for (int i = 0; i < 4; i++)
#pragma unroll
        for (int j = 0; j < 4; j++)
#pragma unroll
            for (int r = 0; r < 4; r++) acc[i][j][r] = 0.0f;

    float4 fa[4];
    uint4  fah[2], fal[2], fb[2];

    auto fetch = [&](int kc) {
        if (AIN == 0) {
#pragma unroll
            for (int p = 0; p < 4; p++)
                fa[p] = *(const float4*)(Afb + (size_t)(p * 32) * KDIM + kc);
        } else {
#pragma unroll
            for (int p = 0; p < 2; p++) {
                fah[p] = *(const uint4*)(Ahb + (size_t)(p * 64) * KDIM + kc);
                fal[p] = *(const uint4*)(Alb + (size_t)(p * 64) * KDIM + kc);
            }
        }
#pragma unroll
        for (int p = 0; p < 2; p++)
            fb[p] = *(const uint4*)(Bfb + (size_t)(p * 64) * KDIM + kc);
    };

    auto store_stage = [&](uint32_t st) {
        if (AIN == 0) {
#pragma unroll
            for (int p = 0; p < 4; p++) {
                uint32_t ad = st + (uint32_t)(arow + p * 32) * 80 + acol * 2;
                float x0 = fa[p].x, x1 = fa[p].y, x2 = fa[p].z, x3 = fa[p].w;
                float h0 = __half2float(__float2half(x0));
                float h1 = __half2float(__float2half(x1));
                float h2 = __half2float(__float2half(x2));
                float h3 = __half2float(__float2half(x3));
                sts64(ad + AH_OFF, packh(x0, x1), packh(x2, x3));
                sts64(ad + AL_OFF, packh(x0 - h0, x1 - h1), packh(x2 - h2, x3 - h3));
            }
        } else {
#pragma unroll
            for (int p = 0; p < 2; p++) {
                uint32_t ad = st + (uint32_t)(hrow + p * 64) * 80 + hcol * 2;
                sts128(ad + AH_OFF, fah[p]);
                sts128(ad + AL_OFF, fal[p]);
            }
        }
#pragma unroll
        for (int p = 0; p < 2; p++) {
            uint32_t bd = st + (uint32_t)(hrow + p * 64) * 80 + hcol * 2;
            sts128(bd + B_OFF, fb[p]);
        }
    };

    fetch(0);
    store_stage(sb);
    __syncthreads();

    const int NIT = KDIM / 32;
    for (int c = 0; c < NIT; c++) {
        const uint32_t st = sb + (uint32_t)(c & 1) * ST_SZ;

        if (c + 1 < NIT) fetch((c + 1) * 32);

#pragma unroll
        for (int ks = 0; ks < 2; ks++) {
            const uint32_t ko = ks * 32;
            uint32_t ah[4][4], bh[4][2], tmpv[4];
#pragma unroll
            for (int mi = 0; mi < 4; mi++)
                ldsm4(st + AH_OFF + aRow + mi * 1280 + ko, ah[mi]);
#pragma unroll
            for (int j = 0; j < 2; j++) {
                ldsm4(st + B_OFF + bRow + j * 1280 + ko, tmpv);
                bh[2*j][0] = tmpv[0]; bh[2*j][1] = tmpv[1];
                bh[2*j+1][0] = tmpv[2]; bh[2*j+1][1] = tmpv[3];
            }
#pragma unroll
            for (int mi = 0; mi < 4; mi++)
#pragma unroll
                for (int nj = 0; nj < 4; nj++)
                    mma_f16(acc[mi][nj], ah[mi], bh[nj]);

            uint32_t al[4][4];
#pragma unroll
            for (int mi = 0; mi < 4; mi++)
                ldsm4(st + AL_OFF + aRow + mi * 1280 + ko, al[mi]);
#pragma unroll
            for (int mi = 0; mi < 4; mi++)
#pragma unroll
                for (int nj = 0; nj < 4; nj++)
                    mma_f16(acc[mi][nj], al[mi], bh[nj]);
        }

        if (c + 1 < NIT) store_stage(sb + (uint32_t)((c + 1) & 1) * ST_SZ);
        __syncthreads();
    }

    const int rbase = m0 + wm * 64 + (lane >> 2);
    const int cbase = n0 + wn * 32 + (lane & 3) * 2;
#pragma unroll
    for (int mi = 0; mi < 4; mi++)
#pragma unroll
        for (int nj = 0; nj < 4; nj++) {
            int r0 = rbase + mi * 16;
            int cc = cbase + nj * 8;
            if (OUTK == 0) {
                *(float2*)(C + (size_t)r0 * N + cc)       = make_float2(acc[mi][nj][0], acc[mi][nj][1]);
                *(float2*)(C + (size_t)(r0 + 8) * N + cc) = make_float2(acc[mi][nj][2], acc[mi][nj][3]);
            } else {
                int bb0 = r0 >> 11, ss0 = r0 & 2047;
                int hh = cc >> 6, dd = cc & 63;
                size_t i0 = (((size_t)(bb0 * NH + hh)) * SS + ss0) * 64 + dd;
                int r1 = r0 + 8;
                int bb1 = r1 >> 11, ss1 = r1 & 2047;
                size_t i1 = (((size_t)(bb1 * NH + hh)) * SS + ss1) * 64 + dd;
                if (OUTK == 1) {
                    split_store_h(Ch, Cl, i0, acc[mi][nj][0] * scale, acc[mi][nj][1] * scale);
                    split_store_h(Ch, Cl, i1, acc[mi][nj][2] * scale, acc[mi][nj][3] * scale);
                } else {
                    *(uint32_t*)(Ch + i0) = packh(acc[mi][nj][0], acc[mi][nj][1]);
                    *(uint32_t*)(Ch + i1) = packh(acc[mi][nj][2], acc[mi][nj][3]);
                }
            }
        }
}

// ---------------------------------------------------------------------------
// HMMA flash attention, fp16 2-term split (Q split / K single, P split / V single)
// ---------------------------------------------------------------------------
#define AT_STRIDE 144
#define KF_OFF 0
#define VF_OFF 9216
#define AT_STAGE 18432
#define ATT_SMEM (2 * AT_STAGE)   // 36864

__global__ __launch_bounds__(256, 1)
void attn_mma(const __half* __restrict__ Qh_, const __half* __restrict__ Ql_,
              const __half* __restrict__ Kf_, const __half* __restrict__ Vf_,
              __half* __restrict__ Ch, __half* __restrict__ Cl)
{
    extern __shared__ char smem[];
    const uint32_t sb = smem_u32(smem);
    const int tid = threadIdx.x, wid = tid >> 5, lane = tid & 31;
    const int bh = blockIdx.y;
    const int b = bh >> 5, hq = bh & 31, hk = hq >> 2;
    const int q0 = blockIdx.x * 128;

    const __half* Qhb = Qh_ + ((size_t)bh * SS + q0) * 64;
    const __half* Qlb = Ql_ + ((size_t)bh * SS + q0) * 64;
    const size_t kvoff = (size_t)(b * HKVn + hk) * SS * 64;
    const __half* Kfb = Kf_ + kvoff;
    const __half* Vfb = Vf_ + kvoff;

    // stage Q (hi at 0, lo at 18432), extract frags, then reuse smem for K/V
    for (int i = tid; i < 1024; i += 256) {
        int r = i >> 3, ch = i & 7;
        *(uint4*)(smem + r * AT_STRIDE + ch * 16)         = *(const uint4*)(Qhb + (size_t)r * 64 + ch * 8);
        *(uint4*)(smem + 18432 + r * AT_STRIDE + ch * 16) = *(const uint4*)(Qlb + (size_t)r * 64 + ch * 8);
    }
    __syncthreads();

    uint32_t qh[4][4], ql[4][4];
    {
        uint32_t aAddr = sb + (uint32_t)(wid * 16 + (lane & 15)) * AT_STRIDE + (lane >> 4) * 16;
#pragma unroll
        for (int kc = 0; kc < 4; kc++) {
            ldsm4(aAddr + kc * 32, qh[kc]);
            ldsm4(aAddr + 18432 + kc * 32, ql[kc]);
        }
    }
    __syncthreads();

    auto load_tile = [&](int kt, uint32_t st) {
        size_t base = (size_t)kt * 64 * 64;
#pragma unroll
        for (int i = tid; i < 512; i += 256) {
            int r = i >> 3, ch = i & 7;
            uint32_t d = st + r * AT_STRIDE + ch * 16;
            size_t s = base + (size_t)r * 64 + ch * 8;
            cp16(d + KF_OFF, Kfb + s);
            cp16(d + VF_OFF, Vfb + s);
        }
    };

    float m0 = -1e30f, m1 = -1e30f, l0 = 0.0f, l1 = 0.0f;
    float ctx[8][4];
#pragma unroll
    for (int j = 0; j < 8; j++)
#pragma unroll
        for (int e = 0; e < 4; e++) ctx[j][e] = 0.0f;

    load_tile(0, sb);
    CP_COMMIT();

    const int NKT = SS / 64;
    for (int kt = 0; kt < NKT; kt++) {
        const uint32_t st = sb + (uint32_t)(kt & 1) * AT_STAGE;
        if (kt + 1 < NKT) {
            load_tile(kt + 1, sb + (uint32_t)((kt + 1) & 1) * AT_STAGE);
            CP_COMMIT();
            cp_wait<1>();
        } else {
            cp_wait<0>();
        }
        __syncthreads();

        // ---- S = Q @ K^T (2-term split), log2 units ----
        float sS[8][4];
#pragma unroll
        for (int j = 0; j < 8; j++)
#pragma unroll
            for (int e = 0; e < 4; e++) sS[j][e] = 0.0f;

        const uint32_t kAddr = st + KF_OFF + (uint32_t)((lane >> 4) * 8 + (lane & 7)) * AT_STRIDE
                             + ((lane >> 3) & 1) * 16;
#pragma unroll
        for (int kc = 0; kc < 4; kc++) {
            uint32_t bK[8][2], t[4];
#pragma unroll
            for (int np = 0; np < 4; np++) {
                ldsm4(kAddr + np * 2304 + kc * 32, t);
                bK[2*np][0] = t[0]; bK[2*np][1] = t[1];
                bK[2*np+1][0] = t[2]; bK[2*np+1][1] = t[3];
            }
#pragma unroll
            for (int nj = 0; nj < 8; nj++) mma_f16(sS[nj], qh[kc], bK[nj]);
#pragma unroll
            for (int nj = 0; nj < 8; nj++) mma_f16(sS[nj], ql[kc], bK[nj]);
        }

        // ---- online softmax (base 2) ----
        float mx0 = -1e30f, mx1 = -1e30f;
#pragma unroll
        for (int j = 0; j < 8; j++) {
            mx0 = fmaxf(mx0, fmaxf(sS[j][0], sS[j][1]));
            mx1 = fmaxf(mx1, fmaxf(sS[j][2], sS[j][3]));
        }
        mx0 = fmaxf(mx0, __shfl_xor_sync(0xffffffffu, mx0, 1));
        mx0 = fmaxf(mx0, __shfl_xor_sync(0xffffffffu, mx0, 2));
        mx1 = fmaxf(mx1, __shfl_xor_sync(0xffffffffu, mx1, 1));
        mx1 = fmaxf(mx1, __shfl_xor_sync(0xffffffffu, mx1, 2));

        float mn0 = fmaxf(m0, mx0), mn1 = fmaxf(m1, mx1);
        float al0 = exp2f(m0 - mn0), al1 = exp2f(m1 - mn1);
        m0 = mn0; m1 = mn1;

        float rs0 = 0.0f, rs1 = 0.0f;
#pragma unroll
        for (int j = 0; j < 8; j++) {
            sS[j][0] = exp2f(sS[j][0] - mn0);
            sS[j][1] = exp2f(sS[j][1] - mn0);
            sS[j][2] = exp2f(sS[j][2] - mn1);
            sS[j][3] = exp2f(sS[j][3] - mn1);
            rs0 += sS[j][0] + sS[j][1];
            rs1 += sS[j][2] + sS[j][3];
        }
        rs0 += __shfl_xor_sync(0xffffffffu, rs0, 1);
        rs0 += __shfl_xor_sync(0xffffffffu, rs0, 2);
        rs1 += __shfl_xor_sync(0xffffffffu, rs1, 1);
        rs1 += __shfl_xor_sync(0xffffffffu, rs1, 2);
        l0 = l0 * al0 + rs0;
        l1 = l1 * al1 + rs1;

#pragma unroll
        for (int j = 0; j < 8; j++) {
            ctx[j][0] *= al0; ctx[j][1] *= al0;
            ctx[j][2] *= al1; ctx[j][3] *= al1;
        }

        // ---- ctx += P @ V (P split, V single) ----
        const uint32_t vAddr = st + VF_OFF + (uint32_t)(lane & 15) * AT_STRIDE + (lane >> 4) * 16;
#pragma unroll
        for (int kc = 0; kc < 4; kc++) {
            float x0 = sS[2*kc][0],   x1 = sS[2*kc][1],   x2 = sS[2*kc][2],   x3 = sS[2*kc][3];
            float y0 = sS[2*kc+1][0], y1 = sS[2*kc+1][1], y2 = sS[2*kc+1][2], y3 = sS[2*kc+1][3];
            uint32_t aPh[4], aPl[4];
            aPh[0] = packh(x0, x1); aPh[1] = packh(x2, x3);
            aPh[2] = packh(y0, y1); aPh[3] = packh(y2, y3);
            float hx0 = __half2float(__float2half(x0));
            float hx1 = __half2float(__float2half(x1));
            float hx2 = __half2float(__float2half(x2));
            float hx3 = __half2float(__float2half(x3));
            float hy0 = __half2float(__float2half(y0));
            float hy1 = __half2float(__float2half(y1));
            float hy2 = __half2float(__float2half(y2));
            float hy3 = __half2float(__float2half(y3));
            aPl[0] = packh(x0 - hx0, x1 - hx1); aPl[1] = packh(x2 - hx2, x3 - hx3);
            aPl[2] = packh(y0 - hy0, y1 - hy1); aPl[3] = packh(y2 - hy2, y3 - hy3);

#pragma unroll
            for (int dp = 0; dp < 4; dp++) {
                uint32_t t[4];
                ldsm4t(vAddr + kc * 2304 + dp * 32, t);
                uint32_t b0[2] = { t[0], t[1] }, b1[2] = { t[2], t[3] };
                mma_f16(ctx[2*dp],   aPh, b0);
                mma_f16(ctx[2*dp+1], aPh, b1);
                mma_f16(ctx[2*dp],   aPl, b0);
                mma_f16(ctx[2*dp+1], aPl, b1);
            }
        }
        __syncthreads();
    }

    // ---- epilogue: normalize, write split fp16 ctx [b, s, hq*64+d] ----
    float inv0 = 1.0f / l0, inv1 = 1.0f / l1;
    int r0 = q0 + wid * 16 + (lane >> 2);
    size_t obase = (size_t)b * SS * DM + (size_t)hq * 64;
#pragma unroll
    for (int nj = 0; nj < 8; nj++) {
        int cc = nj * 8 + (lane & 3) * 2;
        split_store_h(Ch, Cl, obase + (size_t)r0 * DM + cc,
                      ctx[nj][0] * inv0, ctx[nj][1] * inv0);
        split_store_h(Ch, Cl, obase + (size_t)(r0 + 8) * DM + cc,
                      ctx[nj][2] * inv1, ctx[nj][3] * inv1);
    }
}

// ---------------------------------------------------------------------------
extern "C" void kernel_launch(void* const* d_in, const int* in_sizes, int n_in,
                              void* d_out, int out_size)
{
    const float* q  = (const float*)d_in[0];
    const float* k  = (const float*)d_in[1];
    const float* v  = (const float*)d_in[2];
    const float* Wq = (const float*)d_in[3];
    const float* Wk = (const float*)d_in[4];
    const float* Wv = (const float*)d_in[5];
    const float* Wo = (const float*)d_in[6];
    float* out = (float*)d_out;

    __half *Wf, *Ch, *Cl, *Qh, *Ql, *Kf, *Vf;
    cudaGetSymbolAddress((void**)&Wf, g_Wf);
    cudaGetSymbolAddress((void**)&Ch, g_Ch);
    cudaGetSymbolAddress((void**)&Cl, g_Cl);
    cudaGetSymbolAddress((void**)&Qh, g_Qh);
    cudaGetSymbolAddress((void**)&Ql, g_Ql);
    cudaGetSymbolAddress((void**)&Kf, g_Kf);
    cudaGetSymbolAddress((void**)&Vf, g_Vf);

    cudaFuncSetAttribute((const void*)&gemm_hmma<0,1,32>, cudaFuncAttributeMaxDynamicSharedMemorySize, GEMM_SMEM);
    cudaFuncSetAttribute((const void*)&gemm_hmma<0,2,8>,  cudaFuncAttributeMaxDynamicSharedMemorySize, GEMM_SMEM);
    cudaFuncSetAttribute((const void*)&gemm_hmma<1,0,0>,  cudaFuncAttributeMaxDynamicSharedMemorySize, GEMM_SMEM);
    cudaFuncSetAttribute((const void*)&attn_mma,          cudaFuncAttributeMaxDynamicSharedMemorySize, ATT_SMEM);

    dim3 wblk(32, 8);

    // Q projection  (split fp16 out, head-major, pre-scaled)
    wconv<<<dim3(DM / 32, KDIM / 32), wblk>>>(Wq, Wf, DM);
    gemm_hmma<0,1,32><<<dim3(DM / 128, ROWS / 128), 256, GEMM_SMEM>>>(
        q, nullptr, nullptr, Wf, nullptr, Qh, Ql, SCALE_Q, DM);

    // K projection  (single fp16 out)
    wconv<<<dim3(DKV / 32, KDIM / 32), wblk>>>(Wk, Wf, DKV);
    gemm_hmma<0,2,8><<<dim3(DKV / 128, ROWS / 128), 256, GEMM_SMEM>>>(
        k, nullptr, nullptr, Wf, nullptr, Kf, nullptr, 1.0f, DKV);

    // V projection  (single fp16 out)
    wconv<<<dim3(DKV / 32, KDIM / 32), wblk>>>(Wv, Wf, DKV);
    gemm_hmma<0,2,8><<<dim3(DKV / 128, ROWS / 128), 256, GEMM_SMEM>>>(
        v, nullptr, nullptr, Wf, nullptr, Vf, nullptr, 1.0f, DKV);

    // attention (writes split fp16 ctx)
    attn_mma<<<dim3(SS / 128, BB * HQn), 256, ATT_SMEM>>>(Qh, Ql, Kf, Vf, Ch, Cl);

    // output projection (split fp16 A in, fp32 out)
    wconv<<<dim3(DM / 32, KDIM / 32), wblk>>>(Wo, Wf, DM);
    gemm_hmma<1,0,0><<<dim3(DM / 128, ROWS / 128), 256, GEMM_SMEM>>>(
        nullptr, Ch, Cl, Wf, out, nullptr, nullptr, 1.0f, DM);
}